// round 8
// baseline (speedup 1.0000x reference)
#include <cuda_runtime.h>

#define BATCH  16384
#define NNZ    819200
#define KDIM   16
#define VOCAB  1000000
#define CHUNK  128
#define NWARPS (NNZ / CHUNK)     // 6400 (exact)
#define WPB    8
#define NBLK   (NWARPS / WPB)    // 800 (exact)

// accumulator scratch, SoA layout: rows 0..15 = t1_k[r], row 16 = c[r]
__device__ float g_acc[17 * BATCH];

// ---------------------------------------------------------------------------
// dtype detection: words 2i+1 (i < NNZ/2) are in-bounds under both views.
// int64 view -> high words all 0; int32 view -> sorted index vals ~8191 != 0.
// ---------------------------------------------------------------------------
__device__ __forceinline__ int detect_is64(const unsigned int* __restrict__ w) {
    unsigned int acc = 0;
    int base = NNZ / 2 - 8;
#pragma unroll
    for (int i = 0; i < 8; i++) acc |= w[2 * (base + i) + 1];
    return (acc == 0u) ? 1 : 0;
}

template <bool IS64>
__device__ __forceinline__ int ld_i(const void* __restrict__ p, int i) {
    if (IS64) return (int)__ldg((const long long*)p + i);
    return __ldg((const int*)p + i);
}

struct __align__(16) WBuf {
    int    idx[CHUNK];     // 512 B
    float2 fv [CHUNK];     // 1024 B  (.x = feat bits, .y = value)
};

// ---------------------------------------------------------------------------
// Warp processes nnz [ws, ws+128). Segments found via ballot scan over staged
// idx. Lane owns k = lane&15; groups g = lane>>4 interleave nnz. Per-segment
// flush: 1 shfl + 2 atomic instructions. No out[] writes here at all.
// ---------------------------------------------------------------------------
template <bool IS64>
__device__ __forceinline__ void fm_chunk(
        int ws, int lane, WBuf* __restrict__ buf,
        const void* __restrict__ index,
        const void* __restrict__ feats,
        const float* __restrict__ values,
        const float* __restrict__ weights,
        const float* __restrict__ embedding) {
    // ---- stage 128 (idx, feat, value) coalesced ----
#pragma unroll
    for (int t = 0; t < 4; t++) {
        const int o = lane + 32 * t;
        const int j = ws + o;
        buf->idx[o] = ld_i<IS64>(index, j);
        buf->fv[o]  = make_float2(__int_as_float(ld_i<IS64>(feats, j)),
                                  __ldg(values + j));
    }
    __syncwarp();

    const int k = lane & 15;
    const int g = lane >> 4;

    int p = 0;
    while (p < CHUNK) {
        const int r = buf->idx[p];            // uniform (broadcast LDS)

        // ---- segment end via ballot scan, 32 positions at a time ----
        int q = p;
        for (;;) {
            const int  t    = q + lane;
            const bool same = (t < CHUNK) && (buf->idx[t] == r);
            const unsigned bal = __ballot_sync(0xffffffffu, same);
            if (bal == 0xffffffffu) { q += 32; if (q >= CHUNK) { q = CHUNK; break; } }
            else                    { q += __ffs(~bal) - 1; break; }
        }

        // ---- accumulate segment [p, q): 2 nnz per iteration ----
        float t1 = 0.f, c = 0.f;
        for (int j = p + g; j < q; j += 2) {
            const float2 fv = buf->fv[j];     // 16-lane broadcast LDS.64
            const int    f  = __float_as_int(fv.x);
            const float  v  = fv.y;
            const float  e  = __ldg(embedding + (size_t)f * KDIM + k) * v;
            t1 += e;
            c   = fmaf(-0.5f * e, e, c);
            if (k == 0) c = fmaf(__ldg(weights + f), v, c);
        }

        // ---- flush: combine groups, then atomics (REDG) ----
        t1 += __shfl_xor_sync(0xffffffffu, t1, 16);
        if (lane < 16) atomicAdd(&g_acc[lane * BATCH + r], t1);  // 16-lane spread
        atomicAdd(&g_acc[16 * BATCH + r], c);                    // 32-lane same-addr

        p = q;
    }
}

__global__ void __launch_bounds__(256)
fm_main(const void* __restrict__ index,
        const void* __restrict__ feats,
        const float* __restrict__ values,
        const float* __restrict__ weights,
        const float* __restrict__ embedding) {
    __shared__ WBuf bufs[WPB];
    __shared__ int  s_is64;
    if (threadIdx.x == 0) s_is64 = detect_is64((const unsigned int*)index);
    __syncthreads();

    const int warp = (blockIdx.x * blockDim.x + threadIdx.x) >> 5;
    const int lane = threadIdx.x & 31;
    const int ws   = warp * CHUNK;
    WBuf* buf = &bufs[threadIdx.x >> 5];

    if (s_is64) fm_chunk<true >(ws, lane, buf, index, feats, values, weights, embedding);
    else        fm_chunk<false>(ws, lane, buf, index, feats, values, weights, embedding);
}

// ---------------------------------------------------------------------------
// Finish: every row r -> sigmoid(bias + c_r + 0.5 * sum_k t1_k^2).
// Coalesced reads thanks to SoA scratch layout.
// ---------------------------------------------------------------------------
__global__ void __launch_bounds__(256)
finish_kernel(const float* __restrict__ bias, float* __restrict__ out) {
    const int r = blockIdx.x * blockDim.x + threadIdx.x;
    if (r >= BATCH) return;
    float acc = g_acc[16 * BATCH + r];
#pragma unroll
    for (int kk = 0; kk < KDIM; kk++) {
        const float t = g_acc[kk * BATCH + r];
        acc = fmaf(0.5f * t, t, acc);
    }
    const float x = acc + __ldg(bias);
    out[r] = 1.0f / (1.0f + expf(-x));
}

// ---------------------------------------------------------------------------
extern "C" void kernel_launch(void* const* d_in, const int* in_sizes, int n_in,
                              void* d_out, int out_size) {
    const void*  index_p   = nullptr;
    const void*  feats_p   = nullptr;
    const float* values_p  = nullptr;
    const float* bias_p    = nullptr;
    const float* weights_p = nullptr;
    const float* embed_p   = nullptr;

    int triple = 0;
    for (int i = 0; i < n_in; i++) {
        int sz = in_sizes[i];
        if (sz == NNZ) {
            if      (triple == 0) index_p  = d_in[i];
            else if (triple == 1) feats_p  = d_in[i];
            else                  values_p = (const float*)d_in[i];
            triple++;
        } else if (sz == VOCAB) {
            weights_p = (const float*)d_in[i];
        } else if (sz == VOCAB * KDIM) {
            embed_p = (const float*)d_in[i];
        } else if (sz == 1) {
            bias_p = (const float*)d_in[i];   // last size-1 input is bias
        }
    }

    float* out = (float*)d_out;
    (void)out_size;

    void* acc_ptr = nullptr;
    cudaGetSymbolAddress(&acc_ptr, g_acc);
    cudaMemsetAsync(acc_ptr, 0, sizeof(float) * 17 * BATCH, 0);

    fm_main<<<NBLK, 256>>>(index_p, feats_p, values_p, weights_p, embed_p);
    finish_kernel<<<(BATCH + 255) / 256, 256>>>(bias_p, out);
}

// round 9
// speedup vs baseline: 1.4681x; 1.4681x over previous
#include <cuda_runtime.h>

#define BATCH  16384
#define NNZ    819200
#define KDIM   16
#define VOCAB  1000000
#define CAP    256        // staged nnz per super-chunk (covers ~99.9% rows whole)

__device__ int g_row_ptr[BATCH + 1];
__device__ int g_is64;

// ---------------------------------------------------------------------------
// dtype detection: words 2i+1 (i < NNZ/2) are in-bounds under both views.
// int64 view -> high words all 0; int32 view -> sorted index vals ~8191 != 0.
// ---------------------------------------------------------------------------
__device__ __forceinline__ int detect_is64(const unsigned int* __restrict__ w) {
    unsigned int acc = 0;
    int base = NNZ / 2 - 8;
#pragma unroll
    for (int i = 0; i < 8; i++) acc |= w[2 * (base + i) + 1];
    return (acc == 0u) ? 1 : 0;
}

template <bool IS64>
__device__ __forceinline__ int ld_i(const void* __restrict__ p, int i) {
    if (IS64) return (int)__ldg((const long long*)p + i);
    return __ldg((const int*)p + i);
}

__device__ __forceinline__ float warp_sum(float r) {
#pragma unroll
    for (int o = 16; o > 0; o >>= 1)
        r += __shfl_xor_sync(0xffffffffu, r, o);
    return r;
}

// ---------------------------------------------------------------------------
// K1: rowptr via adjacent difference over the sorted index. One coalesced
// pass, fully parallel (measured ~1 us incl. launch).
// ---------------------------------------------------------------------------
__global__ void __launch_bounds__(256)
rowptr_kernel(const void* __restrict__ index) {
    __shared__ int s_is64;
    if (threadIdx.x == 0) {
        int is64 = detect_is64((const unsigned int*)index);
        s_is64 = is64;
        if (blockIdx.x == 0) g_is64 = is64;
    }
    __syncthreads();
    const int is64 = s_is64;

    const int i = blockIdx.x * blockDim.x + threadIdx.x;
    if (i >= NNZ) return;

    int a, b;
    if (is64) {
        a = ld_i<true >(index, i);
        b = (i + 1 < NNZ) ? ld_i<true >(index, i + 1) : BATCH;
    } else {
        a = ld_i<false>(index, i);
        b = (i + 1 < NNZ) ? ld_i<false>(index, i + 1) : BATCH;
    }
    if (i == 0)
        for (int r = 0; r <= a; r++) g_row_ptr[r] = 0;
    for (int r = a + 1; r <= b; r++) g_row_ptr[r] = i + 1;
}

// ---------------------------------------------------------------------------
// K2: warp per row.
//  Phase 1 (stage): coalesced (feat, value) -> smem as (frow, v), padded to
//    a multiple of 8 with v=0; first-order gather folded into this pass.
//  Phase 2 (gather): octet layout (8 groups g x 4 slots m). Iteration t:
//    LDS.64 broadcast of (frow, v) for nnz 8t+g, then LDG.128 of the
//    embedding quarter-row. No cross-iteration deps -> unroll 4 keeps many
//    independent LDG.128s in flight for the warp's whole lifetime.
// ---------------------------------------------------------------------------
struct __align__(16) WBuf { float2 fv[CAP]; };   // 2 KB/warp

template <bool IS64>
__device__ __forceinline__ float fm_row(
        int s, int e, int lane, WBuf* __restrict__ buf,
        const void* __restrict__ feats,
        const float* __restrict__ values,
        const float* __restrict__ weights,
        const float* __restrict__ embedding) {
    const int g = lane >> 2;   // octet position 0..7
    const int m = lane & 3;    // float4 slot: k = 4m .. 4m+3

    float4 t1 = make_float4(0.f, 0.f, 0.f, 0.f);
    float  t2 = 0.f, first = 0.f;

    for (int base = s; base < e; base += CAP) {
        const int n    = min(e - base, CAP);
        const int npad = (n + 7) & ~7;

        // ---- stage (coalesced); fold first-order gather in ----
        for (int o = lane; o < npad; o += 32) {
            int   f = 0;
            float v = 0.f;
            if (o < n) {
                f = ld_i<IS64>(feats, base + o);
                v = __ldg(values + base + o);
                first += __ldg(weights + f) * v;
            }
            buf->fv[o] = make_float2(__int_as_float(f * KDIM), v);
        }
        __syncwarp();

        // ---- gather: independent iterations, deep MLP ----
        const int iters = npad >> 3;
#pragma unroll 4
        for (int t = 0; t < iters; t++) {
            const float2 fv  = buf->fv[8 * t + g];     // 4-lane broadcast
            const int    fr  = __float_as_int(fv.x);
            const float  vv  = fv.y;
            const float4 e4  = __ldg((const float4*)(embedding + fr) + m);
            const float e0 = e4.x * vv, e1 = e4.y * vv,
                        e2 = e4.z * vv, e3 = e4.w * vv;
            t1.x += e0; t1.y += e1; t1.z += e2; t1.w += e3;
            t2 = fmaf(e0, e0, t2); t2 = fmaf(e1, e1, t2);
            t2 = fmaf(e2, e2, t2); t2 = fmaf(e3, e3, t2);
        }
        __syncwarp();
    }

    // reduce t1 over the 8 octet-groups (lane bits 2..4)
#pragma unroll
    for (int o = 4; o <= 16; o <<= 1) {
        t1.x += __shfl_xor_sync(0xffffffffu, t1.x, o);
        t1.y += __shfl_xor_sync(0xffffffffu, t1.y, o);
        t1.z += __shfl_xor_sync(0xffffffffu, t1.z, o);
        t1.w += __shfl_xor_sync(0xffffffffu, t1.w, o);
    }

    // |t1|^2 replicated 8x across g-groups -> coefficient 0.5/8 = 0.0625
    float r = 0.0625f * (t1.x * t1.x + t1.y * t1.y + t1.z * t1.z + t1.w * t1.w)
            - 0.5f * t2 + first;
    return warp_sum(r);
}

__global__ void __launch_bounds__(256)
fm_kernel(const void* __restrict__ feats,
          const float* __restrict__ values,
          const float* __restrict__ weights,
          const float* __restrict__ embedding,
          const float* __restrict__ bias,
          float* __restrict__ out) {
    __shared__ WBuf bufs[8];

    const int warp = (blockIdx.x * blockDim.x + threadIdx.x) >> 5;
    const int lane = threadIdx.x & 31;
    if (warp >= BATCH) return;
    const int b = warp;
    WBuf* buf = &bufs[threadIdx.x >> 5];

    const int s = g_row_ptr[b];
    const int e = g_row_ptr[b + 1];

    float r = 0.f;
    if (e > s) {
        if (g_is64) r = fm_row<true >(s, e, lane, buf, feats, values, weights, embedding);
        else        r = fm_row<false>(s, e, lane, buf, feats, values, weights, embedding);
    }

    if (lane == 0) {
        const float x = r + __ldg(bias);
        out[b] = 1.0f / (1.0f + expf(-x));
    }
}

// ---------------------------------------------------------------------------
extern "C" void kernel_launch(void* const* d_in, const int* in_sizes, int n_in,
                              void* d_out, int out_size) {
    const void*  index_p   = nullptr;
    const void*  feats_p   = nullptr;
    const float* values_p  = nullptr;
    const float* bias_p    = nullptr;
    const float* weights_p = nullptr;
    const float* embed_p   = nullptr;

    int triple = 0;
    for (int i = 0; i < n_in; i++) {
        int sz = in_sizes[i];
        if (sz == NNZ) {
            if      (triple == 0) index_p  = d_in[i];
            else if (triple == 1) feats_p  = d_in[i];
            else                  values_p = (const float*)d_in[i];
            triple++;
        } else if (sz == VOCAB) {
            weights_p = (const float*)d_in[i];
        } else if (sz == VOCAB * KDIM) {
            embed_p = (const float*)d_in[i];
        } else if (sz == 1) {
            bias_p = (const float*)d_in[i];   // last size-1 input is bias
        }
    }

    float* out = (float*)d_out;
    (void)out_size;

    rowptr_kernel<<<(NNZ + 255) / 256, 256>>>(index_p);
    fm_kernel<<<(BATCH * 32 + 255) / 256, 256>>>(feats_p, values_p, weights_p,
                                                 embed_p, bias_p, out);
}